// round 1
// baseline (speedup 1.0000x reference)
#include <cuda_runtime.h>
#include <math.h>

#define BATCH  256
#define PRIOR  60
#define FRAMES 240
#define POSE   768
#define CHUNK  10
#define PRED   180
#define EPS    1e-5f

// ---------------- scratch (static device globals; no allocation) ----------------
__device__ float g_p1[BATCH * PRED * POSE];    // conv1 output
__device__ float g_p2[BATCH * PRED * POSE];    // conv2 output / updated p
__device__ float g_h1[BATCH * FRAMES * POSE];  // post-header intermediate
__device__ float g_tmp[BATCH * POSE];
__device__ float g_mem[BATCH * POSE];
__device__ float g_mem2[BATCH * POSE];
__device__ float g_s1[BATCH * CHUNK];
__device__ float g_penc[BATCH * CHUNK];
__device__ float g_t[POSE * CHUNK];

// ---------------- generic NT GEMM: C[M,N] = A[M,K] @ W[N,K]^T + bias[N] ----------------
// AMODE 0: A row m at A + m*lda
// AMODE 1: concat rows: m -> (b=m/FRAMES, f=m%FRAMES); f<PRIOR ? x-row : p-row
template <int BM, int BN, int BK, int TM, int TN, int AMODE>
__global__ __launch_bounds__((BM / TM) * (BN / TN))
void sgemm_nt(const float* __restrict__ A, long lda,
              const float* __restrict__ A2,
              const float* __restrict__ W,
              const float* __restrict__ bias,
              float* __restrict__ C, int ldc,
              int M, int N, int K)
{
    constexpr int THREADS = (BM / TM) * (BN / TN);
    constexpr int ASLOTS = BM * BK / THREADS;
    constexpr int BSLOTS = BN * BK / THREADS;

    __shared__ float As[BK][BM + 4];
    __shared__ float Bs[BK][BN + 4];

    const int tid = threadIdx.x;
    const int bm = blockIdx.y * BM;
    const int bn = blockIdx.x * BN;
    const int tx = tid % (BN / TN);
    const int ty = tid / (BN / TN);

    // Precompute per-slot row pointers (fixed across the K loop)
    const float* arow[ASLOTS];
    int akl[ASLOTS], aml[ASLOTS];
#pragma unroll
    for (int j = 0; j < ASLOTS; ++j) {
        int s = tid + j * THREADS;
        akl[j] = s % BK;
        aml[j] = s / BK;
        int m = bm + aml[j];
        const float* rp;
        if (AMODE == 1) {
            int bb = m / FRAMES, f = m % FRAMES;
            rp = (f < PRIOR) ? (A2 + ((long)bb * PRIOR + f) * POSE)
                             : (A  + ((long)bb * PRED  + (f - PRIOR)) * POSE);
        } else {
            rp = A + (long)m * lda;
        }
        arow[j] = rp;
    }
    const float* brow[BSLOTS];
    int bkl[BSLOTS], bnl[BSLOTS];
#pragma unroll
    for (int j = 0; j < BSLOTS; ++j) {
        int s = tid + j * THREADS;
        bkl[j] = s % BK;
        bnl[j] = s / BK;
        brow[j] = W + (long)(bn + bnl[j]) * K;
    }

    float acc[TM][TN];
#pragma unroll
    for (int i = 0; i < TM; ++i)
#pragma unroll
        for (int j = 0; j < TN; ++j) acc[i][j] = 0.f;

    for (int k0 = 0; k0 < K; k0 += BK) {
#pragma unroll
        for (int j = 0; j < ASLOTS; ++j) {
            int k = k0 + akl[j];
            int m = bm + aml[j];
            float v = (k < K && m < M) ? arow[j][k] : 0.f;
            As[akl[j]][aml[j]] = v;
        }
#pragma unroll
        for (int j = 0; j < BSLOTS; ++j) {
            int k = k0 + bkl[j];
            float v = (k < K && (bn + bnl[j]) < N) ? brow[j][k] : 0.f;
            Bs[bkl[j]][bnl[j]] = v;
        }
        __syncthreads();
#pragma unroll
        for (int kk = 0; kk < BK; ++kk) {
            float a[TM], b[TN];
#pragma unroll
            for (int i = 0; i < TM; ++i) a[i] = As[kk][ty * TM + i];
#pragma unroll
            for (int j = 0; j < TN; ++j) b[j] = Bs[kk][tx * TN + j];
#pragma unroll
            for (int i = 0; i < TM; ++i)
#pragma unroll
                for (int j = 0; j < TN; ++j) acc[i][j] += a[i] * b[j];
        }
        __syncthreads();
    }

#pragma unroll
    for (int i = 0; i < TM; ++i) {
        int m = bm + ty * TM + i;
        if (m >= M) continue;
#pragma unroll
        for (int j = 0; j < TN; ++j) {
            int n = bn + tx * TN + j;
            if (n < N) C[(long)m * ldc + n] = acc[i][j] + bias[n];
        }
    }
}

// ---------------- conv1d(k=3,p=1) over pose axis + ReLU + BN (eval) ----------------
// Per batch b: P[b][o][h] = bn(relu( sum_{i,kk} W[o, i*3+kk] * X[b, i, h+kk-1] + cb[o] ))
template <int BM, int BN, int BK, int TM, int TN>
__global__ __launch_bounds__((BM / TM) * (BN / TN))
void conv_bn_kernel(const float* __restrict__ Wt, int CIN,
                    const float* __restrict__ X,
                    const float* __restrict__ cb,
                    const float* __restrict__ gg, const float* __restrict__ bb,
                    const float* __restrict__ mm, const float* __restrict__ vv,
                    float* __restrict__ P)
{
    constexpr int THREADS = (BM / TM) * (BN / TN);
    static_assert(THREADS == BN, "B-tile loader assumes THREADS == BN");
    constexpr int ASLOTS = BM * BK / THREADS;

    const int K = CIN * 3;
    __shared__ float As[BK][BM + 4];
    __shared__ float Bs[BK][BN + 4];

    const int tid = threadIdx.x;
    const int bm = blockIdx.y * BM;
    const int bn = blockIdx.x * BN;
    const int bz = blockIdx.z;
    const float* Xb = X + (long)bz * CIN * POSE;
    const int tx = tid % (BN / TN);
    const int ty = tid / (BN / TN);

    float acc[TM][TN];
#pragma unroll
    for (int i = 0; i < TM; ++i)
#pragma unroll
        for (int j = 0; j < TN; ++j) acc[i][j] = 0.f;

    for (int k0 = 0; k0 < K; k0 += BK) {
#pragma unroll
        for (int j = 0; j < ASLOTS; ++j) {
            int s = tid + j * THREADS;
            int kl = s % BK, ml = s / BK;
            int k = k0 + kl, o = bm + ml;
            float v = (k < K && o < PRED) ? Wt[(long)o * K + k] : 0.f;
            As[kl][ml] = v;
        }
#pragma unroll
        for (int j = 0; j < BK; ++j) {
            int kk = k0 + j;
            float v = 0.f;
            if (kk < K) {
                int i = kk / 3;
                int dlt = kk - 3 * i - 1;
                int h = bn + tid + dlt;
                if (h >= 0 && h < POSE) v = Xb[(long)i * POSE + h];
            }
            Bs[j][tid] = v;
        }
        __syncthreads();
#pragma unroll
        for (int kk = 0; kk < BK; ++kk) {
            float a[TM], b[TN];
#pragma unroll
            for (int i = 0; i < TM; ++i) a[i] = As[kk][ty * TM + i];
#pragma unroll
            for (int j = 0; j < TN; ++j) b[j] = Bs[kk][tx * TN + j];
#pragma unroll
            for (int i = 0; i < TM; ++i)
#pragma unroll
                for (int j = 0; j < TN; ++j) acc[i][j] += a[i] * b[j];
        }
        __syncthreads();
    }

#pragma unroll
    for (int i = 0; i < TM; ++i) {
        int o = bm + ty * TM + i;
        if (o >= PRED) continue;
        float sc = gg[o] * rsqrtf(vv[o] + EPS);
        float mo = mm[o], bo = bb[o], co = cb[o];
        float* Pr = P + (long)bz * PRED * POSE + (long)o * POSE;
#pragma unroll
        for (int j = 0; j < TN; ++j) {
            int h = bn + tx * TN + j;
            float y = acc[i][j] + co;
            y = fmaxf(y, 0.f);
            Pr[h] = (y - mo) * sc + bo;
        }
    }
}

// ---------------- SP memory gate ----------------
// score[b,c] = <mem[b,:], p[b,c,:]>; sig = sigmoid(score);
// p[b,c,:] = sig*p + (1-sig)*mem   for c < CHUNK
__global__ void sp_gate_kernel(const float* __restrict__ mem, float* __restrict__ p)
{
    int b = blockIdx.x;
    int tid = threadIdx.x;          // 320 threads = 10 warps
    int w = tid >> 5, lane = tid & 31;
    __shared__ float sig_s[CHUNK];

    const float* pm = mem + (long)b * POSE;
    const float* pc = p + (long)b * PRED * POSE + (long)w * POSE;
    float s = 0.f;
    for (int d = lane; d < POSE; d += 32) s += pm[d] * pc[d];
#pragma unroll
    for (int o = 16; o; o >>= 1) s += __shfl_xor_sync(0xffffffffu, s, o);
    if (lane == 0) sig_s[w] = 1.f / (1.f + expf(-s));
    __syncthreads();

    float* pb = p + (long)b * PRED * POSE;
    for (int idx = tid; idx < CHUNK * POSE; idx += 320) {
        int c = idx / POSE, d = idx - c * POSE;
        float g = sig_s[c];
        pb[idx] = g * pb[idx] + (1.f - g) * pm[d];
    }
}

// ---------------- TM: t[d,c] = sum_b mem2[b,d] * penc[b,c] ----------------
__global__ void tm_t_kernel(const float* __restrict__ mem2,
                            const float* __restrict__ penc,
                            float* __restrict__ t)
{
    int d = blockIdx.x;             // POSE blocks, 64 threads
    int tid = threadIdx.x;
    float acc[CHUNK];
#pragma unroll
    for (int c = 0; c < CHUNK; ++c) acc[c] = 0.f;
    for (int b = tid; b < BATCH; b += 64) {
        float m = mem2[(long)b * POSE + d];
        const float* pr = penc + (long)b * CHUNK;
#pragma unroll
        for (int c = 0; c < CHUNK; ++c) acc[c] += m * pr[c];
    }
    __shared__ float red[64][CHUNK];
#pragma unroll
    for (int c = 0; c < CHUNK; ++c) red[tid][c] = acc[c];
    __syncthreads();
    for (int off = 32; off >= 1; off >>= 1) {
        if (tid < off)
#pragma unroll
            for (int c = 0; c < CHUNK; ++c) red[tid][c] += red[tid + off][c];
        __syncthreads();
    }
    if (tid == 0)
#pragma unroll
        for (int c = 0; c < CHUNK; ++c) t[(long)d * CHUNK + c] = red[0][c];
}

// ---------------- TM apply: score2 = mem2 @ t; softmax over c; p[:, :CHUNK] *= (1+soft) ----
__global__ void tm_apply_kernel(const float* __restrict__ mem2,
                                const float* __restrict__ t,
                                float* __restrict__ p)
{
    int b = blockIdx.x;
    int tid = threadIdx.x;          // 256 threads
    float acc[CHUNK];
#pragma unroll
    for (int c = 0; c < CHUNK; ++c) acc[c] = 0.f;
    const float* mb = mem2 + (long)b * POSE;
    for (int d = tid; d < POSE; d += 256) {
        float m = mb[d];
        const float* tr = t + (long)d * CHUNK;
#pragma unroll
        for (int c = 0; c < CHUNK; ++c) acc[c] += m * tr[c];
    }
    __shared__ float red[256][CHUNK];
    __shared__ float soft[CHUNK];
#pragma unroll
    for (int c = 0; c < CHUNK; ++c) red[tid][c] = acc[c];
    __syncthreads();
    for (int off = 128; off >= 1; off >>= 1) {
        if (tid < off)
#pragma unroll
            for (int c = 0; c < CHUNK; ++c) red[tid][c] += red[tid + off][c];
        __syncthreads();
    }
    if (tid == 0) {
        float mx = red[0][0];
#pragma unroll
        for (int c = 1; c < CHUNK; ++c) mx = fmaxf(mx, red[0][c]);
        float sum = 0.f;
        float e[CHUNK];
#pragma unroll
        for (int c = 0; c < CHUNK; ++c) { e[c] = expf(red[0][c] - mx); sum += e[c]; }
        float inv = 1.f / sum;
#pragma unroll
        for (int c = 0; c < CHUNK; ++c) soft[c] = e[c] * inv;
    }
    __syncthreads();
    float* pb = p + (long)b * PRED * POSE;
    for (int idx = tid; idx < CHUNK * POSE; idx += 256) {
        int c = idx / POSE;
        pb[idx] *= (1.f + soft[c]);
    }
}

// ---------------- host launcher ----------------
extern "C" void kernel_launch(void* const* d_in, const int* in_sizes, int n_in,
                              void* d_out, int out_size)
{
    (void)in_sizes; (void)n_in; (void)out_size;

    const float* x       = (const float*)d_in[0];
    const float* conv1_w = (const float*)d_in[1];
    const float* conv1_b = (const float*)d_in[2];
    const float* bn1_g   = (const float*)d_in[3];
    const float* bn1_b   = (const float*)d_in[4];
    const float* bn1_m   = (const float*)d_in[5];
    const float* bn1_v   = (const float*)d_in[6];
    const float* conv2_w = (const float*)d_in[7];
    const float* conv2_b = (const float*)d_in[8];
    const float* bn2_g   = (const float*)d_in[9];
    const float* bn2_b   = (const float*)d_in[10];
    const float* bn2_m   = (const float*)d_in[11];
    const float* bn2_v   = (const float*)d_in[12];
    const float* sp_w1   = (const float*)d_in[13];
    const float* sp_b1   = (const float*)d_in[14];
    const float* sp_w2   = (const float*)d_in[15];
    const float* sp_b2   = (const float*)d_in[16];
    const float* tmc_w1  = (const float*)d_in[17];
    const float* tmc_b1  = (const float*)d_in[18];
    const float* tmc_w2  = (const float*)d_in[19];
    const float* tmc_b2  = (const float*)d_in[20];
    const float* tmm_w1  = (const float*)d_in[21];
    const float* tmm_b1  = (const float*)d_in[22];
    const float* tmm_w2  = (const float*)d_in[23];
    const float* tmm_b2  = (const float*)d_in[24];
    const float* post_w1 = (const float*)d_in[25];
    const float* post_b1 = (const float*)d_in[26];
    const float* post_w2 = (const float*)d_in[27];
    const float* post_b2 = (const float*)d_in[28];

    float *p1, *p2, *h1, *tmp, *mem, *mem2, *s1, *penc, *t;
    cudaGetSymbolAddress((void**)&p1,   g_p1);
    cudaGetSymbolAddress((void**)&p2,   g_p2);
    cudaGetSymbolAddress((void**)&h1,   g_h1);
    cudaGetSymbolAddress((void**)&tmp,  g_tmp);
    cudaGetSymbolAddress((void**)&mem,  g_mem);
    cudaGetSymbolAddress((void**)&mem2, g_mem2);
    cudaGetSymbolAddress((void**)&s1,   g_s1);
    cudaGetSymbolAddress((void**)&penc, g_penc);
    cudaGetSymbolAddress((void**)&t,    g_t);

    // 1) conv1 + relu + bn1 : x[B,60,768] -> p1[B,180,768]
    {
        dim3 grid(POSE / 128, (PRED + 63) / 64, BATCH);
        conv_bn_kernel<64, 128, 16, 8, 8><<<grid, 128>>>(
            conv1_w, PRIOR, x, conv1_b, bn1_g, bn1_b, bn1_m, bn1_v, p1);
    }
    // 2) conv2 + relu + bn2 : p1 -> p2
    {
        dim3 grid(POSE / 128, (PRED + 63) / 64, BATCH);
        conv_bn_kernel<64, 128, 16, 8, 8><<<grid, 128>>>(
            conv2_w, PRED, p1, conv2_b, bn2_g, bn2_b, bn2_m, bn2_v, p2);
    }
    // 3) sp encoder: tail -> tmp -> mem
    sgemm_nt<32, 128, 16, 4, 8, 0><<<dim3(POSE / 128, BATCH / 32), 128>>>(
        x + (PRIOR - CHUNK) * POSE, (long)PRIOR * POSE, nullptr,
        sp_w1, sp_b1, tmp, POSE, BATCH, POSE, CHUNK * POSE);
    sgemm_nt<32, 128, 16, 4, 8, 0><<<dim3(POSE / 128, BATCH / 32), 128>>>(
        tmp, POSE, nullptr, sp_w2, sp_b2, mem, POSE, BATCH, POSE, POSE);
    // 4) sigmoid gate on p2[:, :CHUNK]
    sp_gate_kernel<<<BATCH, CHUNK * 32>>>(mem, p2);
    // 5) tmc encoder: tail -> tmp -> mem2
    sgemm_nt<32, 128, 16, 4, 8, 0><<<dim3(POSE / 128, BATCH / 32), 128>>>(
        x + (PRIOR - CHUNK) * POSE, (long)PRIOR * POSE, nullptr,
        tmc_w1, tmc_b1, tmp, POSE, BATCH, POSE, CHUNK * POSE);
    sgemm_nt<32, 128, 16, 4, 8, 0><<<dim3(POSE / 128, BATCH / 32), 128>>>(
        tmp, POSE, nullptr, tmc_w2, tmc_b2, mem2, POSE, BATCH, POSE, POSE);
    // 6) tmm encoder on updated p2[:, :CHUNK] -> s1 -> penc
    sgemm_nt<32, 128, 16, 4, 8, 0><<<dim3(1, BATCH / 32), 128>>>(
        p2, (long)PRED * POSE, nullptr,
        tmm_w1, tmm_b1, s1, CHUNK, BATCH, CHUNK, CHUNK * POSE);
    sgemm_nt<32, 128, 16, 4, 8, 0><<<dim3(1, BATCH / 32), 128>>>(
        s1, CHUNK, nullptr, tmm_w2, tmm_b2, penc, CHUNK, BATCH, CHUNK, CHUNK);
    // 7) t = mem2^T @ penc ; score2 = mem2 @ t ; softmax ; scale p2[:, :CHUNK]
    tm_t_kernel<<<POSE, 64>>>(mem2, penc, t);
    tm_apply_kernel<<<BATCH, 256>>>(mem2, t, p2);
    // 8) post header: concat(x, p2) @ W1^T + b1 -> h1 ; h1 @ W2^T + b2 -> out
    sgemm_nt<128, 128, 16, 8, 8, 1><<<dim3(POSE / 128, BATCH * FRAMES / 128), 256>>>(
        p2, 0, x, post_w1, post_b1, h1, POSE, BATCH * FRAMES, POSE, POSE);
    sgemm_nt<128, 128, 16, 8, 8, 0><<<dim3(POSE / 128, BATCH * FRAMES / 128), 256>>>(
        h1, POSE, nullptr, post_w2, post_b2, (float*)d_out, POSE, BATCH * FRAMES, POSE, POSE);
}